// round 2
// baseline (speedup 1.0000x reference)
#include <cuda_runtime.h>
#include <math.h>

#define NN 50000
#define EE 800000
#define GG 128
#define FIN 768
#define HH 128
#define CC 2

// ---------------- scratch (no allocations allowed) ----------------
__device__ __align__(16) float g_z[(size_t)NN * HH];   // post-GEMM features
__device__ __align__(16) float g_h[(size_t)NN * HH];   // post-aggregation features
__device__ float g_ssrc[NN];
__device__ float g_sdst[NN];
__device__ int   g_deg[NN];
__device__ int   g_cursor[NN];
__device__ int   g_rowstart[NN + 1];
__device__ int   g_csr[EE];
__device__ __align__(16) float g_pool[GG * HH];
__device__ float g_cnt[GG];

__device__ __forceinline__ float selu_f(float x) {
    const float sc = 1.0507009873554805f, al = 1.6732632423543772f;
    return x > 0.0f ? sc * x : sc * al * expm1f(x);
}

// ---------------- init: zero the accumulators ----------------
__global__ void k_init() {
    int i = blockIdx.x * blockDim.x + threadIdx.x;
    if (i < NN) { g_deg[i] = 0; g_cursor[i] = 0; }
    if (i < GG * HH) g_pool[i] = 0.0f;
    if (i < GG) g_cnt[i] = 0.0f;
}

// ---------------- CSR build (by dst), int32 edge indices ----------------
__global__ void k_hist(const int* __restrict__ ei) {
    int i = blockIdx.x * blockDim.x + threadIdx.x;
    if (i >= EE) return;
    unsigned d = (unsigned)ei[EE + i];
    if (d < NN) atomicAdd(&g_deg[d], 1);
}

__global__ void k_scan() {
    __shared__ int sh[1024];
    __shared__ int carry_s;
    int tid = threadIdx.x;
    if (tid == 0) carry_s = 0;
    __syncthreads();
    int nchunks = (NN + 1023) / 1024;
    for (int c = 0; c < nchunks; c++) {
        int i = c * 1024 + tid;
        int v = (i < NN) ? g_deg[i] : 0;
        sh[tid] = v;
        __syncthreads();
        for (int off = 1; off < 1024; off <<= 1) {
            int t = (tid >= off) ? sh[tid - off] : 0;
            __syncthreads();
            sh[tid] += t;
            __syncthreads();
        }
        int inc = sh[tid] + carry_s;
        if (i < NN) g_rowstart[i + 1] = inc;
        __syncthreads();
        if (tid == 1023) carry_s = inc;
        __syncthreads();
    }
    if (tid == 0) g_rowstart[0] = 0;
}

__global__ void k_scatter(const int* __restrict__ ei) {
    int i = blockIdx.x * blockDim.x + threadIdx.x;
    if (i >= EE) return;
    unsigned d = (unsigned)ei[EE + i];
    unsigned s = (unsigned)ei[i];
    if (d >= NN || s >= NN) return;
    int pos = atomicAdd(&g_cursor[d], 1);
    g_csr[g_rowstart[d] + pos] = (int)s;
}

// ---------------- SGEMM: C[M,128] = A[M,K] @ B[K,128], writes g_z ----------------
// block: 256 threads, tile 64(M) x 128(N), K-tile 16
__global__ void k_gemm(const float* __restrict__ Aext, const float* __restrict__ B,
                       int use_gh, int M, int K) {
    const float* A = use_gh ? (const float*)g_h : Aext;
    __shared__ float As[16][64];
    __shared__ float Bs[16][128];
    int tid = threadIdx.x;
    int m0 = blockIdx.x * 64;
    int tx = tid & 31, ty = tid >> 5;
    float acc[8][4];
#pragma unroll
    for (int r = 0; r < 8; r++)
#pragma unroll
        for (int j = 0; j < 4; j++) acc[r][j] = 0.0f;

    int am = tid >> 2, ak = (tid & 3) * 4;
    for (int k0 = 0; k0 < K; k0 += 16) {
        float4 av = make_float4(0.f, 0.f, 0.f, 0.f);
        int row = m0 + am;
        if (row < M) av = *(const float4*)(A + (size_t)row * K + k0 + ak);
        As[ak + 0][am] = av.x;
        As[ak + 1][am] = av.y;
        As[ak + 2][am] = av.z;
        As[ak + 3][am] = av.w;
#pragma unroll
        for (int r = 0; r < 2; r++) {
            int i = tid + r * 256;      // 0..511 float4s of the B tile
            int bk = i >> 5, bn = (i & 31) * 4;
            *(float4*)&Bs[bk][bn] = *(const float4*)(B + (size_t)(k0 + bk) * HH + bn);
        }
        __syncthreads();
#pragma unroll
        for (int k = 0; k < 16; k++) {
            float4 b  = *(float4*)&Bs[k][tx * 4];
            float4 a0 = *(float4*)&As[k][ty * 8];
            float4 a1 = *(float4*)&As[k][ty * 8 + 4];
            float ar[8] = {a0.x, a0.y, a0.z, a0.w, a1.x, a1.y, a1.z, a1.w};
#pragma unroll
            for (int r = 0; r < 8; r++) {
                acc[r][0] = fmaf(ar[r], b.x, acc[r][0]);
                acc[r][1] = fmaf(ar[r], b.y, acc[r][1]);
                acc[r][2] = fmaf(ar[r], b.z, acc[r][2]);
                acc[r][3] = fmaf(ar[r], b.w, acc[r][3]);
            }
        }
        __syncthreads();
    }
#pragma unroll
    for (int r = 0; r < 8; r++) {
        int row = m0 + ty * 8 + r;
        if (row < M)
            *(float4*)(g_z + (size_t)row * HH + tx * 4) =
                make_float4(acc[r][0], acc[r][1], acc[r][2], acc[r][3]);
    }
}

// ---------------- per-node attention scores ----------------
__global__ void k_score(const float* __restrict__ asrc, const float* __restrict__ adst) {
    int gt = blockIdx.x * blockDim.x + threadIdx.x;
    int node = gt >> 5, lane = gt & 31;
    if (node >= NN) return;
    float4 zv = *(const float4*)(g_z + (size_t)node * HH + lane * 4);
    float4 a1 = *(const float4*)(asrc + lane * 4);
    float4 a2 = *(const float4*)(adst + lane * 4);
    float s1 = zv.x * a1.x + zv.y * a1.y + zv.z * a1.z + zv.w * a1.w;
    float s2 = zv.x * a2.x + zv.y * a2.y + zv.z * a2.z + zv.w * a2.w;
#pragma unroll
    for (int off = 16; off > 0; off >>= 1) {
        s1 += __shfl_xor_sync(0xffffffffu, s1, off);
        s2 += __shfl_xor_sync(0xffffffffu, s2, off);
    }
    if (lane == 0) { g_ssrc[node] = s1; g_sdst[node] = s2; }
}

// ---------------- warp-per-dst edge softmax + aggregation + bias + selu ----------------
__global__ void k_agg(const float* __restrict__ bias) {
    int gt = blockIdx.x * blockDim.x + threadIdx.x;
    int d = gt >> 5, lane = gt & 31;
    if (d >= NN) return;
    int start = g_rowstart[d], end = g_rowstart[d + 1];
    float sd = g_sdst[d];

    // pass 1: max over incoming edges (post-leakyrelu)
    float m = -3.4e38f;
    for (int i = start + lane; i < end; i += 32) {
        float e = g_ssrc[g_csr[i]] + sd;
        e = e > 0.f ? e : 0.2f * e;
        m = fmaxf(m, e);
    }
#pragma unroll
    for (int off = 16; off > 0; off >>= 1)
        m = fmaxf(m, __shfl_xor_sync(0xffffffffu, m, off));

    // pass 2: exp-sum + weighted feature gather (all 32 lanes on feature dim)
    float4 acc = make_float4(0.f, 0.f, 0.f, 0.f);
    float denom = 0.f;
    for (int i = start; i < end; i++) {
        int s = g_csr[i];                       // broadcast load
        float e = g_ssrc[s] + sd;
        e = e > 0.f ? e : 0.2f * e;
        float w = __expf(e - m);
        denom += w;
        float4 zv = *(const float4*)(g_z + (size_t)s * HH + lane * 4);
        acc.x = fmaf(w, zv.x, acc.x);
        acc.y = fmaf(w, zv.y, acc.y);
        acc.z = fmaf(w, zv.z, acc.z);
        acc.w = fmaf(w, zv.w, acc.w);
    }
    float inv = 1.0f / (denom + 1e-9f);
    float4 bv = *(const float4*)(bias + lane * 4);
    float4 r;
    r.x = selu_f(fmaf(acc.x, inv, bv.x));
    r.y = selu_f(fmaf(acc.y, inv, bv.y));
    r.z = selu_f(fmaf(acc.z, inv, bv.z));
    r.w = selu_f(fmaf(acc.w, inv, bv.w));
    *(float4*)(g_h + (size_t)d * HH + lane * 4) = r;
}

// ---------------- global mean pool (sums + counts via atomics) ----------------
__global__ void k_pool(const int* __restrict__ batch) {
    int gt = blockIdx.x * blockDim.x + threadIdx.x;
    int node = gt >> 5, lane = gt & 31;
    if (node >= NN) return;
    unsigned g = (unsigned)batch[node];
    if (g >= GG) return;
    float4 hv = *(const float4*)(g_h + (size_t)node * HH + lane * 4);
    atomicAdd(&g_pool[g * HH + lane * 4 + 0], hv.x);
    atomicAdd(&g_pool[g * HH + lane * 4 + 1], hv.y);
    atomicAdd(&g_pool[g * HH + lane * 4 + 2], hv.z);
    atomicAdd(&g_pool[g * HH + lane * 4 + 3], hv.w);
    if (lane == 0) atomicAdd(&g_cnt[g], 1.0f);
}

// ---------------- head: mean, fc1+selu, fc2, log_softmax; one block per graph ----------------
__global__ void k_head(const float* __restrict__ fc1w, const float* __restrict__ fc1b,
                       const float* __restrict__ fc2w, const float* __restrict__ fc2b,
                       float* __restrict__ out) {
    int g = blockIdx.x;
    int t = threadIdx.x;                 // 128 threads
    __shared__ float p[HH];
    __shared__ float hid[HH];
    float c = fmaxf(g_cnt[g], 1.0f);
    p[t] = g_pool[g * HH + t] / c;
    __syncthreads();
    float acc = fc1b[t];
    for (int i = 0; i < HH; i++) acc = fmaf(p[i], fc1w[i * HH + t], acc);
    hid[t] = selu_f(acc);
    __syncthreads();
    if (t < CC) {
        float l = fc2b[t];
        for (int i = 0; i < HH; i++) l = fmaf(hid[i], fc2w[i * CC + t], l);
        p[t] = l;
    }
    __syncthreads();
    if (t == 0) {
        float l0 = p[0], l1 = p[1];
        float mx = fmaxf(l0, l1);
        float lse = mx + logf(__expf(l0 - mx) + __expf(l1 - mx));
        out[g * CC + 0] = l0 - lse;
        out[g * CC + 1] = l1 - lse;
    }
}

// ---------------- launch ----------------
extern "C" void kernel_launch(void* const* d_in, const int* in_sizes, int n_in,
                              void* d_out, int out_size) {
    const float* x     = (const float*)d_in[0];
    const int*   ei    = (const int*)d_in[1];     // int32 (JAX x64 disabled)
    const int*   batch = (const int*)d_in[2];
    const float* W1    = (const float*)d_in[3];
    const float* a1s   = (const float*)d_in[4];
    const float* a1d   = (const float*)d_in[5];
    const float* b1    = (const float*)d_in[6];
    const float* W2    = (const float*)d_in[7];
    const float* a2s   = (const float*)d_in[8];
    const float* a2d   = (const float*)d_in[9];
    const float* b2    = (const float*)d_in[10];
    const float* fc1w  = (const float*)d_in[11];
    const float* fc1b  = (const float*)d_in[12];
    const float* fc2w  = (const float*)d_in[13];
    const float* fc2b  = (const float*)d_in[14];
    float* out = (float*)d_out;

    int nb_nodes_warp = (NN * 32 + 255) / 256;
    int nb_e = (EE + 255) / 256;

    k_init<<<(NN + 255) / 256, 256>>>();
    k_hist<<<nb_e, 256>>>(ei);
    k_scan<<<1, 1024>>>();
    k_scatter<<<nb_e, 256>>>(ei);

    // layer 1
    k_gemm<<<(NN + 63) / 64, 256>>>(x, W1, 0, NN, FIN);
    k_score<<<nb_nodes_warp, 256>>>(a1s, a1d);
    k_agg<<<nb_nodes_warp, 256>>>(b1);

    // layer 2
    k_gemm<<<(NN + 63) / 64, 256>>>(nullptr, W2, 1, NN, HH);
    k_score<<<nb_nodes_warp, 256>>>(a2s, a2d);
    k_agg<<<nb_nodes_warp, 256>>>(b2);

    // pool + head
    k_pool<<<nb_nodes_warp, 256>>>(batch);
    k_head<<<GG, HH>>>(fc1w, fc1b, fc2w, fc2b, out);
}